// round 15
// baseline (speedup 1.0000x reference)
#include <cuda_runtime.h>
#include <cstdint>
#include <math.h>

#define VOC 4096
#define EMBD 256
#define HID 512
#define BB  64
#define TT  1024
#define G4H 2048
#define BT  (BB*TT)                       // 65536
#define BTV ((long long)BT*VOC)           // 268435456
#define HP  544                           // padded h row: 8 slices x 68 floats

typedef unsigned long long ull;

// ---------------- static device scratch (no runtime allocation) ----------------
__device__ __align__(16) float g_G[(size_t)VOC*G4H];   // 32 MB : emb@W_ih^T + (b_ih+b_hh)
__device__ __align__(16) float g_hs[(size_t)BT*HID];   // 128 MB: hidden states, row (t*64+b)
__device__ __align__(16) float g_hp[2][BB*HP];         // double-buffered h, slice-padded [b][8][68]
__device__ ull      g_amax[BT];                        // packed (float,idx) argmax per row
__device__ unsigned g_ctr[4*TT];                       // per-batch-quarter barrier counters
__device__ int      g_xmode;                           // 1 = x is int32, 0 = x is int64

// ---------------- packed f32x2 + sync helpers ----------------
__device__ __forceinline__ void fma2(ull& d, ull a, ull b){
    asm("fma.rn.f32x2 %0, %1, %2, %0;" : "+l"(d) : "l"(a), "l"(b));
}
__device__ __forceinline__ ull pk2(float x, float y){
    ull r; asm("mov.b64 %0, {%1,%2};" : "=l"(r) : "f"(x), "f"(y)); return r;
}
__device__ __forceinline__ float2 up2(ull v){
    float2 r; asm("mov.b64 {%0,%1}, %2;" : "=f"(r.x), "=f"(r.y) : "l"(v)); return r;
}
__device__ __forceinline__ float hsum2(ull v){
    float2 p = up2(v); return p.x + p.y;
}
__device__ __forceinline__ float redux16(float v){
    v += __shfl_xor_sync(0xFFFFFFFFu, v, 1, 32);
    v += __shfl_xor_sync(0xFFFFFFFFu, v, 2, 32);
    v += __shfl_xor_sync(0xFFFFFFFFu, v, 4, 32);
    v += __shfl_xor_sync(0xFFFFFFFFu, v, 8, 32);
    return v;
}
__device__ __forceinline__ void arrive_release(unsigned* p){
    asm volatile("red.release.gpu.global.add.u32 [%0], 1;" :: "l"(p) : "memory");
}
__device__ __forceinline__ unsigned ld_acquire(const unsigned* p){
    unsigned v; asm volatile("ld.acquire.gpu.global.u32 %0, [%1];" : "=r"(v) : "l"(p) : "memory");
    return v;
}
// monotone float->u32; pack with complemented index so max => (max val, lowest idx)
__device__ __forceinline__ ull packam(float v, int n){
    unsigned u = __float_as_uint(v);
    u = (u & 0x80000000u) ? ~u : (u | 0x80000000u);
    return ((ull)u << 32) | (unsigned)(VOC - 1 - n);
}

// ---------------- dtype detect + init (every replay) ----------------
__global__ void detect_k(const int* __restrict__ x32){
    if (threadIdx.x == 0){
        int nz = 0;
        for (int i = 0; i < 128; i++) nz += (x32[2*i + 1] != 0);
        g_xmode = (nz > 0) ? 1 : 0;   // all-odd-words-zero => little-endian int64 tokens
    }
}
__global__ void init_k(){
    int i = blockIdx.x*blockDim.x + threadIdx.x;
    int n = blockDim.x*gridDim.x;
    for (int p = i; p < BB*HP; p += n) g_hp[0][p] = 0.f;
    for (int p = i; p < BT;    p += n) g_amax[p] = 0ull;
    for (int p = i; p < 4*TT;  p += n) g_ctr[p] = 0u;
}

// ---------------- SGEMM-NT: double-buffered smem + register prefetch -----------
// BM=BN=128, BK=16, 256 threads, 8x8 micro-tile via f32x2. ONE sync per k-tile.
// flags: 1 = write C, 2 = permute out row m -> (m%64)*TT + m/64, 4 = fused argmax
__global__ __launch_bounds__(256, 2) void gemm_k(
    const float* __restrict__ A, const float* __restrict__ B,
    const float* __restrict__ bias1, const float* __restrict__ bias2,
    float* __restrict__ C, int M, int N, int K, int flags)
{
    __shared__ __align__(16) float smem[2][4224];   // per buffer: As 2112 | Bs 2112
    const int m0 = blockIdx.x*128, n0 = blockIdx.y*128;
    const int tid = threadIdx.x;
    const int tm = tid >> 4, tn = tid & 15;
    const int rowA = tid >> 2, kq = tid & 3;

    const float* Ap = A + (size_t)(m0 + rowA)*K + kq*4;
    const float* Bp = B + (size_t)(n0 + rowA)*K + kq*4;
    const size_t o64 = (size_t)64*K;

    ull acc[8][4];
    #pragma unroll
    for (int i = 0; i < 8; i++)
        #pragma unroll
        for (int j = 0; j < 4; j++) acc[i][j] = 0ull;

    // prologue: stage tile 0 into registers
    float4 va0 = *(const float4*)(Ap);
    float4 va1 = *(const float4*)(Ap + o64);
    float4 vb0 = *(const float4*)(Bp);
    float4 vb1 = *(const float4*)(Bp + o64);

    int cur = 0;
    for (int kt = 0; kt < K; kt += 16){
        float* As = smem[cur];
        float* Bs = smem[cur] + 2112;
        As[(kq*4+0)*132+rowA] = va0.x; As[(kq*4+1)*132+rowA] = va0.y;
        As[(kq*4+2)*132+rowA] = va0.z; As[(kq*4+3)*132+rowA] = va0.w;
        As[(kq*4+0)*132+rowA+64] = va1.x; As[(kq*4+1)*132+rowA+64] = va1.y;
        As[(kq*4+2)*132+rowA+64] = va1.z; As[(kq*4+3)*132+rowA+64] = va1.w;
        Bs[(kq*4+0)*132+rowA] = vb0.x; Bs[(kq*4+1)*132+rowA] = vb0.y;
        Bs[(kq*4+2)*132+rowA] = vb0.z; Bs[(kq*4+3)*132+rowA] = vb0.w;
        Bs[(kq*4+0)*132+rowA+64] = vb1.x; Bs[(kq*4+1)*132+rowA+64] = vb1.y;
        Bs[(kq*4+2)*132+rowA+64] = vb1.z; Bs[(kq*4+3)*132+rowA+64] = vb1.w;
        __syncthreads();

        if (kt + 16 < K){   // prefetch next tile (LDGs overlap the compute below)
            va0 = *(const float4*)(Ap + kt + 16);
            va1 = *(const float4*)(Ap + o64 + kt + 16);
            vb0 = *(const float4*)(Bp + kt + 16);
            vb1 = *(const float4*)(Bp + o64 + kt + 16);
        }

        #pragma unroll
        for (int k = 0; k < 16; k++){
            const float* ap = &As[k*132 + tm*8];
            float4 a0 = *(const float4*)ap;
            float4 a1 = *(const float4*)(ap + 4);
            const ulonglong2* bp = (const ulonglong2*)&Bs[k*132 + tn*8];
            ulonglong2 bq0 = bp[0], bq1 = bp[1];
            ull bb0 = bq0.x, bb1 = bq0.y, bb2 = bq1.x, bb3 = bq1.y;
            float aa[8] = {a0.x,a0.y,a0.z,a0.w,a1.x,a1.y,a1.z,a1.w};
            #pragma unroll
            for (int i = 0; i < 8; i++){
                ull ad = pk2(aa[i], aa[i]);
                fma2(acc[i][0], ad, bb0); fma2(acc[i][1], ad, bb1);
                fma2(acc[i][2], ad, bb2); fma2(acc[i][3], ad, bb3);
            }
        }
        cur ^= 1;           // next tile writes the other buffer (no second sync)
    }

    float bv[8];
    {
        const float* b1p = bias1 + n0 + tn*8;
        #pragma unroll
        for (int c = 0; c < 8; c++) bv[c] = b1p[c];
        if (bias2){
            const float* b2p = bias2 + n0 + tn*8;
            #pragma unroll
            for (int c = 0; c < 8; c++) bv[c] += b2p[c];
        }
    }
    const bool wr = flags & 1, pm = flags & 2, am = flags & 4;
    ull best[8];
    #pragma unroll
    for (int i = 0; i < 8; i++){
        int m = m0 + tm*8 + i;
        float v[8];
        #pragma unroll
        for (int jp = 0; jp < 4; jp++){
            float2 f = up2(acc[i][jp]);
            v[2*jp]   = f.x + bv[2*jp];
            v[2*jp+1] = f.y + bv[2*jp+1];
        }
        if (wr){
            size_t orow = pm ? (size_t)((m & 63)*TT + (m >> 6)) : (size_t)m;
            float4* dst = (float4*)(C + orow*(size_t)N + n0 + tn*8);
            dst[0] = make_float4(v[0],v[1],v[2],v[3]);
            dst[1] = make_float4(v[4],v[5],v[6],v[7]);
        }
        if (am){
            ull bl = packam(v[0], n0 + tn*8);
            #pragma unroll
            for (int c = 1; c < 8; c++){
                ull p = packam(v[c], n0 + tn*8 + c);
                if (p > bl) bl = p;
            }
            best[i] = bl;
        }
    }
    if (am){
        __syncthreads();
        ull* red = (ull*)&smem[0][0];        // 128*16 ull = 16384 B fits buffer 0
        #pragma unroll
        for (int i = 0; i < 8; i++) red[(tm*8+i)*16 + tn] = best[i];
        __syncthreads();
        if (tid < 128){
            ull b = red[tid*16];
            #pragma unroll
            for (int c = 1; c < 16; c++){
                ull p = red[tid*16 + c];
                if (p > b) b = p;
            }
            atomicMax(&g_amax[m0 + tid], b);
        }
    }
}

// ---------------- persistent LSTM recurrence: 128 blocks x 256 threads ----------
// Block = (jg in 32) x (bq in 4): 64 gate rows (16 j) x 16 batches.
// Thread = (rg in 16, ks in 16): 4 rows x 32 k of W_hh in registers ->
// each 16B h vector feeds 8 FFMA2 (2 MAC/B), halving LDS.128 traffic vs 2-row map.
// 4-level shfl reduction over the 16 k-lanes. Per-quarter 32-arrival barrier.
#define SM_LSTM ((16*HP + 16*68)*4)      // 34816 + 4352 = 39168 B
__global__ __launch_bounds__(256, 1) void lstm_k(const void* __restrict__ xraw,
                                                 const float* __restrict__ Whh)
{
    extern __shared__ float hsm[];
    float* gbuf = hsm + 16*HP;           // [16 b][68] gate sums (rows 0..63 used)
    const int tid = threadIdx.x;
    const int jg  = blockIdx.x >> 2;     // 0..31 : j-group of 16
    const int bq  = blockIdx.x & 3;      // 0..3  : batch quarter of 16
    const int ks  = tid & 15;            // k-slice of 32
    const int rg  = tid >> 4;            // row-quad 0..15 (rows 4rg..4rg+3 of 64)
    const int xmode = g_xmode;
    unsigned* ctr = g_ctr + bq*TT;       // this quarter's barrier counters

    // ---- W_hh slice into registers (once): 4 rows x 32 k = 4x16 ull ----
    ull w0[16], w1[16], w2[16], w3[16];
    {
        int r0 = 4*rg;
        int gate  = r0 >> 4;
        int jbase = jg*16 + (r0 & 15);                  // rows r0..r0+3 same gate
        const float* p0 = Whh + (size_t)(gate*HID + jbase+0)*HID + ks*32;
        const float* p1 = Whh + (size_t)(gate*HID + jbase+1)*HID + ks*32;
        const float* p2 = Whh + (size_t)(gate*HID + jbase+2)*HID + ks*32;
        const float* p3 = Whh + (size_t)(gate*HID + jbase+3)*HID + ks*32;
        #pragma unroll
        for (int i = 0; i < 8; i++){
            float4 a = *(const float4*)(p0 + i*4);
            float4 b = *(const float4*)(p1 + i*4);
            float4 c = *(const float4*)(p2 + i*4);
            float4 d = *(const float4*)(p3 + i*4);
            w0[2*i] = pk2(a.x,a.y); w0[2*i+1] = pk2(a.z,a.w);
            w1[2*i] = pk2(b.x,b.y); w1[2*i+1] = pk2(b.z,b.w);
            w2[2*i] = pk2(c.x,c.y); w2[2*i+1] = pk2(c.z,c.w);
            w3[2*i] = pk2(d.x,d.y); w3[2*i+1] = pk2(d.z,d.w);
        }
    }

    // h smem offset of this thread's 32-k slice within a batch row (slice-padded)
    const int koff = (ks >> 1)*68 + (ks & 1)*32;

    // epilogue mapping: thread owns (b, j) every step -> c in register
    const int eb    = tid >> 4;                 // local b 0..15
    const int ejl   = tid & 15;                 // local j 0..15
    const int bglob = bq*16 + eb;
    const int jglob = jg*16 + ejl;
    float c_reg = 0.f;

    for (int t = 0; t < TT; t++){
        // ---- stage this block's 16 batches of h (straight float4 copy, L2) ----
        {
            const float4* src = (const float4*)(g_hp[t & 1] + (size_t)(bq*16)*HP);
            float4* dst = (float4*)hsm;
            #pragma unroll
            for (int l = 0; l < 9; l++){
                int i = tid + l*256;            // 16*544/4 = 2176 float4
                if (i < 2176) dst[i] = __ldcg(src + i);
            }
        }
        __syncthreads();

        // ---- prefetch token + gate-bias gather (consumed in epilogue) ----
        long long xv;
        if (xmode) xv = (long long)((const int*)xraw)[(size_t)bglob*TT + t];
        else       xv = ((const long long*)xraw)[(size_t)bglob*TT + t];
        xv &= (VOC - 1);
        const float* Gb = g_G + (size_t)xv * G4H + jglob;
        float pgi = Gb[0];
        float pgf = Gb[HID];
        float pgg = Gb[2*HID];
        float pgo = Gb[3*HID];

        // ---- 64 rows x 16 b: batch-pairs, 4 rows per thread ----
        #pragma unroll 1
        for (int bp = 0; bp < 8; bp++){
            const ulonglong2* h0 = (const ulonglong2*)(hsm + (2*bp  )*HP + koff);
            const ulonglong2* h1 = (const ulonglong2*)(hsm + (2*bp+1)*HP + koff);
            ull a00=0ull,a01=0ull,a02=0ull,a03=0ull;
            ull a10=0ull,a11=0ull,a12=0ull,a13=0ull;
            #pragma unroll
            for (int i = 0; i < 8; i++){
                ulonglong2 v0 = h0[i];
                fma2(a00, v0.x, w0[2*i]); fma2(a00, v0.y, w0[2*i+1]);
                fma2(a01, v0.x, w1[2*i]); fma2(a01, v0.y, w1[2*i+1]);
                fma2(a02, v0.x, w2[2*i]); fma2(a02, v0.y, w2[2*i+1]);
                fma2(a03, v0.x, w3[2*i]); fma2(a03, v0.y, w3[2*i+1]);
                ulonglong2 v1 = h1[i];
                fma2(a10, v1.x, w0[2*i]); fma2(a10, v1.y, w0[2*i+1]);
                fma2(a11, v1.x, w1[2*i]); fma2(a11, v1.y, w1[2*i+1]);
                fma2(a12, v1.x, w2[2*i]); fma2(a12, v1.y, w2[2*i+1]);
                fma2(a13, v1.x, w3[2*i]); fma2(a13, v1.y, w3[2*i+1]);
            }
            float s00 = redux16(hsum2(a00));
            float s01 = redux16(hsum2(a01));
            float s02 = redux16(hsum2(a02));
            float s03 = redux16(hsum2(a03));
            float s10 = redux16(hsum2(a10));
            float s11 = redux16(hsum2(a11));
            float s12 = redux16(hsum2(a12));
            float s13 = redux16(hsum2(a13));
            if (ks == 0){
                int r = 4*rg;
                *(float4*)(gbuf + (2*bp  )*68 + r) = make_float4(s00,s01,s02,s03);
                *(float4*)(gbuf + (2*bp+1)*68 + r) = make_float4(s10,s11,s12,s13);
            }
        }
        __syncthreads();

        // ---- epilogue: activations, c/h update (rows: gate*16 + jloc) ----
        {
            float di = gbuf[eb*68 +  0 + ejl] + pgi;
            float df = gbuf[eb*68 + 16 + ejl] + pgf;
            float dg = gbuf[eb*68 + 32 + ejl] + pgg;
            float dv = gbuf[eb*68 + 48 + ejl] + pgo;
            float si = 1.f/(1.f + expf(-di));
            float sf = 1.f/(1.f + expf(-df));
            float tg = tanhf(dg);
            float so = 1.f/(1.f + expf(-dv));
            c_reg = sf * c_reg + si * tg;
            float h = so * tanhf(c_reg);
            g_hs[((size_t)t*BB + bglob)*HID + jglob] = h;
            g_hp[(t+1) & 1][(size_t)bglob*HP + (jglob >> 6)*68 + (jglob & 63)] = h;
        }

        // ---- per-quarter barrier (32 arrivals): release arrive + acquire poll ----
        __syncthreads();
        if (tid == 0){
            arrive_release(&ctr[t]);
            while (ld_acquire(&ctr[t]) < 32u) { }
        }
        __syncthreads();
    }
}

// ---------------- decode argmax, write predictions --------------------------
__global__ void writer_k(float* out, long long out_size){
    int m = blockIdx.x*blockDim.x + threadIdx.x;
    if (m >= BT) return;
    int idx = VOC - 1 - (int)(g_amax[m] & 0xFFFFFFFFull);
    int b = m & 63, tt = m >> 6;
    long long orow = (long long)b*TT + tt;
    if (out_size >= BTV + BT){
        out[BTV + orow] = (float)idx;              // logits + preds concatenated (f32)
    } else if (out_size < BTV && out_size >= BT){
        if (g_xmode) ((int*)out)[orow] = idx;      // preds-only, int32 world
        else ((long long*)out)[orow] = (long long)idx; // preds-only, int64 world
    }
}

extern "C" void kernel_launch(void* const* d_in, const int* in_sizes, int n_in,
                              void* d_out, int out_size)
{
    const void* x        = d_in[0];
    // d_in[1] = lens : unused by the reference computation
    const float* emb     = (const float*)d_in[2];
    const float* W_ih    = (const float*)d_in[3];
    const float* W_hh    = (const float*)d_in[4];
    const float* b_ih    = (const float*)d_in[5];
    const float* b_hh    = (const float*)d_in[6];
    const float* W_proj  = (const float*)d_in[7];
    const float* b_proj  = (const float*)d_in[8];
    (void)in_sizes; (void)n_in;

    float *pG, *pHS;
    cudaGetSymbolAddress((void**)&pG,  g_G);
    cudaGetSymbolAddress((void**)&pHS, g_hs);
    cudaFuncSetAttribute(lstm_k,
                         cudaFuncAttributeMaxDynamicSharedMemorySize, SM_LSTM);

    detect_k<<<1, 32>>>((const int*)x);
    init_k<<<256, 256>>>();

    // G = emb @ W_ih^T + (b_ih + b_hh)   [4096 x 2048], K=256
    gemm_k<<<dim3(VOC/128, G4H/128), 256>>>(emb, W_ih, b_ih, b_hh, pG,
                                            VOC, G4H, EMBD, /*flags=*/1);

    // persistent LSTM recurrence (single kernel, per-quarter barriers)
    lstm_k<<<128, 256, SM_LSTM>>>(x, W_hh);

    // logits = hs @ W_proj^T + b_proj    [65536 x 4096], K=512 (+ fused argmax)
    int flags = 4 | 2 | (((long long)out_size >= BTV) ? 1 : 0);
    gemm_k<<<dim3(BT/128, VOC/128), 256>>>(pHS, W_proj, b_proj, nullptr,
                                           (float*)d_out, BT, VOC, HID, flags);

    writer_k<<<BT/256, 256>>>((float*)d_out, (long long)out_size);
}